// round 4
// baseline (speedup 1.0000x reference)
#include <cuda_runtime.h>
#include <cstddef>

// Problem constants
#define NN    4096          // nodes
#define BB    4             // batch
#define CC    32            // channels
#define TT    12            // time
#define FF    1536          // BT*C features per node
#define DCAP  256           // per-row neighbor capacity (max degree ~120)

// ---------------- scratch (device globals; no allocations allowed) ----------
__device__ float g_dinv[NN];
__device__ int   g_len [NN];
__device__ int   g_col [NN * DCAP];
__device__ float g_val [NN * DCAP];
__device__ float g_h  [(size_t)NN * FF];   // x transposed: h[n][(b*12+t)*32+c]
__device__ float g_t1 [(size_t)NN * FF];   // Tx1
__device__ float g_tx2[(size_t)NN * FF];   // Tx2

// ---------------- K1: degrees -> d^{-1/2} -----------------------------------
__global__ void k_degree(const float* __restrict__ adj) {
    int m = blockIdx.x;
    const float* row = adj + (size_t)m * NN;
    float s = 0.f;
    for (int j = threadIdx.x; j < NN; j += 256) s += row[j];
    __shared__ float red[8];
    #pragma unroll
    for (int o = 16; o; o >>= 1) s += __shfl_down_sync(0xffffffffu, s, o);
    if ((threadIdx.x & 31) == 0) red[threadIdx.x >> 5] = s;
    __syncthreads();
    if (threadIdx.x < 8) {
        float v = red[threadIdx.x];
        #pragma unroll
        for (int o = 4; o; o >>= 1) v += __shfl_down_sync(0xffu, v, o);
        if (threadIdx.x == 0) g_dinv[m] = (v > 0.f) ? rsqrtf(v) : 0.f;
    }
}

// ---------------- K2: deterministic CSR build (warp per row) -----------------
__global__ void k_build(const float* __restrict__ adj) {
    int warp = threadIdx.x >> 5;
    int lane = threadIdx.x & 31;
    int m = blockIdx.x * 8 + warp;
    const float* row = adj + (size_t)m * NN;
    float dm = g_dinv[m];
    int*   cl = g_col + m * DCAP;
    float* vl = g_val + m * DCAP;
    int base = 0;
    for (int j0 = 0; j0 < NN; j0 += 32) {
        int j = j0 + lane;
        float a = row[j];
        unsigned mask = __ballot_sync(0xffffffffu, a != 0.f);
        if (a != 0.f) {
            int pos = base + __popc(mask & ((1u << lane) - 1u));
            if (pos < DCAP) {
                cl[pos] = j;
                vl[pos] = dm * a * g_dinv[j];   // norm_adj entry
            }
        }
        base += __popc(mask);
    }
    if (lane == 0) g_len[m] = base < DCAP ? base : DCAP;
}

// ---------------- K3: transpose x[B,C,N,T] -> h[n][f] ------------------------
// tile: 16 nodes, one b per block. smem padded (193 = 192+1) for bank spread.
__global__ void k_transpose(const float* __restrict__ x) {
    __shared__ float sm[32][193];
    int n0 = blockIdx.x * 16;
    int b  = blockIdx.y;
    // load: per channel c, a contiguous span of 16*12 = 192 floats
    for (int idx = threadIdx.x; idx < 32 * 192; idx += 256) {
        int c = idx / 192, r = idx % 192;   // r = n_local*12 + t
        sm[c][r] = x[(((size_t)(b * 32 + c)) * NN + n0) * TT + r];
    }
    __syncthreads();
    // store: consecutive idx vary c fastest -> coalesced 128B writes
    for (int idx = threadIdx.x; idx < 32 * 192; idx += 256) {
        int nl  = idx / 384;
        int rem = idx % 384;
        int t = rem >> 5;
        int c = rem & 31;
        g_h[(size_t)(n0 + nl) * FF + (b * TT + t) * 32 + c] = sm[c][nl * TT + t];
    }
}

// ---------------- K4: Tx1 = h - norm_adj * h ---------------------------------
__global__ void __launch_bounds__(128) k_spmm1() {
    int m  = blockIdx.y;
    int f0 = blockIdx.x * 512 + threadIdx.x * 4;
    __shared__ int   s_col[DCAP];
    __shared__ float s_val[DCAP];
    int len = g_len[m];
    for (int i = threadIdx.x; i < len; i += 128) {
        s_col[i] = g_col[m * DCAP + i];
        s_val[i] = g_val[m * DCAP + i];
    }
    __syncthreads();
    float4 a0 = make_float4(0.f, 0.f, 0.f, 0.f);
    float4 a1 = make_float4(0.f, 0.f, 0.f, 0.f);
    int i = 0;
    for (; i + 4 <= len; i += 4) {
        float4 v0 = *(const float4*)(g_h + (size_t)s_col[i    ] * FF + f0);
        float4 v1 = *(const float4*)(g_h + (size_t)s_col[i + 1] * FF + f0);
        float4 v2 = *(const float4*)(g_h + (size_t)s_col[i + 2] * FF + f0);
        float4 v3 = *(const float4*)(g_h + (size_t)s_col[i + 3] * FF + f0);
        float c0 = s_val[i], c1 = s_val[i+1], c2 = s_val[i+2], c3 = s_val[i+3];
        a0.x += c0*v0.x; a0.y += c0*v0.y; a0.z += c0*v0.z; a0.w += c0*v0.w;
        a1.x += c1*v1.x; a1.y += c1*v1.y; a1.z += c1*v1.z; a1.w += c1*v1.w;
        a0.x += c2*v2.x; a0.y += c2*v2.y; a0.z += c2*v2.z; a0.w += c2*v2.w;
        a1.x += c3*v3.x; a1.y += c3*v3.y; a1.z += c3*v3.z; a1.w += c3*v3.w;
    }
    for (; i < len; i++) {
        float4 v = *(const float4*)(g_h + (size_t)s_col[i] * FF + f0);
        float c = s_val[i];
        a0.x += c*v.x; a0.y += c*v.y; a0.z += c*v.z; a0.w += c*v.w;
    }
    float4 hm = *(const float4*)(g_h + (size_t)m * FF + f0);
    float4 r;
    r.x = hm.x - (a0.x + a1.x);
    r.y = hm.y - (a0.y + a1.y);
    r.z = hm.z - (a0.z + a1.z);
    r.w = hm.w - (a0.w + a1.w);
    *(float4*)(g_t1 + (size_t)m * FF + f0) = r;
}

// ---------------- K5: Tx2 = 2*(Tx1 - norm_adj*Tx1) - h -----------------------
__global__ void __launch_bounds__(128) k_spmm2() {
    int m  = blockIdx.y;
    int f0 = blockIdx.x * 512 + threadIdx.x * 4;
    __shared__ int   s_col[DCAP];
    __shared__ float s_val[DCAP];
    int len = g_len[m];
    for (int i = threadIdx.x; i < len; i += 128) {
        s_col[i] = g_col[m * DCAP + i];
        s_val[i] = g_val[m * DCAP + i];
    }
    __syncthreads();
    float4 a0 = make_float4(0.f, 0.f, 0.f, 0.f);
    float4 a1 = make_float4(0.f, 0.f, 0.f, 0.f);
    int i = 0;
    for (; i + 4 <= len; i += 4) {
        float4 v0 = *(const float4*)(g_t1 + (size_t)s_col[i    ] * FF + f0);
        float4 v1 = *(const float4*)(g_t1 + (size_t)s_col[i + 1] * FF + f0);
        float4 v2 = *(const float4*)(g_t1 + (size_t)s_col[i + 2] * FF + f0);
        float4 v3 = *(const float4*)(g_t1 + (size_t)s_col[i + 3] * FF + f0);
        float c0 = s_val[i], c1 = s_val[i+1], c2 = s_val[i+2], c3 = s_val[i+3];
        a0.x += c0*v0.x; a0.y += c0*v0.y; a0.z += c0*v0.z; a0.w += c0*v0.w;
        a1.x += c1*v1.x; a1.y += c1*v1.y; a1.z += c1*v1.z; a1.w += c1*v1.w;
        a0.x += c2*v2.x; a0.y += c2*v2.y; a0.z += c2*v2.z; a0.w += c2*v2.w;
        a1.x += c3*v3.x; a1.y += c3*v3.y; a1.z += c3*v3.z; a1.w += c3*v3.w;
    }
    for (; i < len; i++) {
        float4 v = *(const float4*)(g_t1 + (size_t)s_col[i] * FF + f0);
        float c = s_val[i];
        a0.x += c*v.x; a0.y += c*v.y; a0.z += c*v.z; a0.w += c*v.w;
    }
    float4 t1m = *(const float4*)(g_t1 + (size_t)m * FF + f0);
    float4 hm  = *(const float4*)(g_h  + (size_t)m * FF + f0);
    float4 r;
    r.x = 2.f * (t1m.x - (a0.x + a1.x)) - hm.x;
    r.y = 2.f * (t1m.y - (a0.y + a1.y)) - hm.y;
    r.z = 2.f * (t1m.z - (a0.z + a1.z)) - hm.z;
    r.w = 2.f * (t1m.w - (a0.w + a1.w)) - hm.w;
    *(float4*)(g_tx2 + (size_t)m * FF + f0) = r;
}

// ---------------- K6: out = Tx0*W0 + Tx1*W1 + Tx2*W2 + bias, transposed back -
// block: fixed b, 32 nodes, all 12 t -> 384 threads, one (n,t) row each.
__global__ void __launch_bounds__(384) k_out(const float* __restrict__ w,
                                             const float* __restrict__ bias,
                                             float* __restrict__ out) {
    __shared__ float sW[3 * 32 * 32];   // [k][c][co]
    __shared__ float sB[32];
    for (int idx = threadIdx.x; idx < 3 * 32 * 32; idx += 384) sW[idx] = w[idx];
    if (threadIdx.x < 32) sB[threadIdx.x] = bias[threadIdx.x];
    __syncthreads();

    int b  = blockIdx.y;
    int nl = threadIdx.x / 12;
    int t  = threadIdx.x % 12;
    int n  = blockIdx.x * 32 + nl;

    size_t fbase = (size_t)n * FF + (b * TT + t) * 32;
    const float* ph = g_h   + fbase;
    const float* p1 = g_t1  + fbase;
    const float* p2 = g_tx2 + fbase;

    float acc[32];
    #pragma unroll
    for (int co = 0; co < 32; co++) acc[co] = sB[co];

    #pragma unroll
    for (int c4 = 0; c4 < 8; c4++) {
        float4 A0 = *(const float4*)(ph + c4 * 4);
        float4 A1 = *(const float4*)(p1 + c4 * 4);
        float4 A2 = *(const float4*)(p2 + c4 * 4);
        #pragma unroll
        for (int cc = 0; cc < 4; cc++) {
            int c = c4 * 4 + cc;
            float a0 = ((const float*)&A0)[cc];
            float a1 = ((const float*)&A1)[cc];
            float a2 = ((const float*)&A2)[cc];
            const float4* w0 = (const float4*)(sW +            c * 32);
            const float4* w1 = (const float4*)(sW + 32 * 32 +  c * 32);
            const float4* w2 = (const float4*)(sW + 2*32*32 +  c * 32);
            #pragma unroll
            for (int q = 0; q < 8; q++) {
                float4 W0 = w0[q], W1 = w1[q], W2 = w2[q];
                acc[q*4+0] += a0*W0.x + a1*W1.x + a2*W2.x;
                acc[q*4+1] += a0*W0.y + a1*W1.y + a2*W2.y;
                acc[q*4+2] += a0*W0.z + a1*W1.z + a2*W2.z;
                acc[q*4+3] += a0*W0.w + a1*W1.w + a2*W2.w;
            }
        }
    }
    // out[b][co][n][t]; warp's (n,t) rows are contiguous along n*12+t -> coalesced
    float* po = out + ((size_t)(b * 32) * NN + n) * TT + t;
    #pragma unroll
    for (int co = 0; co < 32; co++) po[(size_t)co * NN * TT] = acc[co];
}

// ---------------- launch -----------------------------------------------------
extern "C" void kernel_launch(void* const* d_in, const int* in_sizes, int n_in,
                              void* d_out, int out_size) {
    const float* x    = (const float*)d_in[0];   // [4,32,4096,12]
    const float* adj  = (const float*)d_in[1];   // [4096,4096]
    const float* w    = (const float*)d_in[2];   // [3,32,32]
    const float* bias = (const float*)d_in[3];   // [32]
    float* out = (float*)d_out;                  // [4,32,4096,12]

    k_degree   <<<NN, 256>>>(adj);
    k_build    <<<NN / 8, 256>>>(adj);
    k_transpose<<<dim3(NN / 16, BB), 256>>>(x);
    k_spmm1    <<<dim3(3, NN), 128>>>();
    k_spmm2    <<<dim3(3, NN), 128>>>();
    k_out      <<<dim3(NN / 32, BB), 384>>>(w, bias, out);
}